// round 8
// baseline (speedup 1.0000x reference)
#include <cuda_runtime.h>
#include <cstdint>

#define BATCH     512
#define SIZE_IN   1024
#define SIZE_OUT  256
#define NQ        16

#define BT        64                 // batch tile per CTA
#define ISPLIT    37                 // 8 * 37 = 296 = 148 SMs * 2 CTAs exactly
#define ICHUNKMAX 28                 // ceil(1024/37)
#define NTHREADS  512
#define DYN_SMEM  65536              // 2 phase-buffers x 32 KB (2 features x 16 rows x 1 KB)

// out[b,o] = bias[o]  (atomic accumulation target)
__global__ void il_init_out(const float* __restrict__ bias, float* __restrict__ out) {
    int i = blockIdx.x * blockDim.x + threadIdx.x;
    if (i < BATCH * SIZE_OUT) out[i] = bias[i & (SIZE_OUT - 1)];
}

__device__ __forceinline__ void mbar_init(uint32_t mb, uint32_t count) {
    asm volatile("mbarrier.init.shared.b64 [%0], %1;" :: "r"(mb), "r"(count) : "memory");
}
__device__ __forceinline__ void mbar_arrive(uint32_t mb) {
    asm volatile("mbarrier.arrive.shared::cta.b64 _, [%0];" :: "r"(mb) : "memory");
}
__device__ __forceinline__ void mbar_wait(uint32_t mb, uint32_t parity) {
    asm volatile(
        "{\n\t.reg .pred P;\n"
        "WL%=:\n\t"
        "mbarrier.try_wait.parity.acquire.cta.shared::cta.b64 P, [%0], %1, 0x989680;\n\t"
        "@!P bra WL%=;\n\t}"
        :: "r"(mb), "r"(parity) : "memory");
}

// Stage nf (1..2) features starting at i0: nf*16 rows of 1 KB via cp.async.bulk.
__device__ __forceinline__ void stage_phase(uint32_t sdst, const float* __restrict__ table,
                                            int i0, int nf, uint32_t mb) {
    asm volatile("mbarrier.arrive.expect_tx.shared::cta.b64 _, [%0], %1;"
                 :: "r"(mb), "r"((uint32_t)nf * 16384u) : "memory");
    for (int f = 0; f < nf; f++) {
        #pragma unroll
        for (int q = 0; q < NQ; q++) {
            const void* src = table + ((size_t)q * SIZE_IN + i0 + f) * SIZE_OUT;
            asm volatile(
                "cp.async.bulk.shared::cta.global.mbarrier::complete_tx::bytes [%0], [%1], %2, [%3];"
                :: "r"(sdst + (uint32_t)f * 16384u + (uint32_t)q * 1024u),
                   "l"(src), "r"(1024u), "r"(mb) : "memory");
        }
    }
}

// One CTA: 64 batches x (27..28) features x 256 outputs.
// Ring-2 of 32 KB stages (2 features each). full/empty mbarrier pipeline:
// consumers never hit a block barrier; only t0 waits for "all readers done".
__global__ __launch_bounds__(NTHREADS, 2)
void il_main(const float* __restrict__ x,
             const int* __restrict__ indices,   // JAX canonicalizes int64 -> int32
             const float* __restrict__ table,
             float* __restrict__ out) {
    extern __shared__ __align__(1024) float sW[];   // 2 x 8192 floats
    __shared__ float2 sxq[BT][ICHUNKMAX];            // {x, float-bits of q*256}
    __shared__ __align__(8) unsigned long long mbar_store[4];  // full0, full1, empty0, empty1

    const int b0  = blockIdx.x * BT;
    const int lo  = (int)(((long long)blockIdx.y * SIZE_IN) / ISPLIT);
    const int hi  = (int)(((long long)(blockIdx.y + 1) * SIZE_IN) / ISPLIT);
    const int len = hi - lo;             // 27 or 28
    const int nph = (len + 1) >> 1;      // 14
    const int t   = threadIdx.x;
    const int og  = t & 63;              // output columns og*4 .. og*4+3
    const int bg  = t >> 6;              // batches bg*8 .. bg*8+7

    uint32_t full[2], empty[2];
    full[0]  = (uint32_t)__cvta_generic_to_shared(&mbar_store[0]);
    full[1]  = (uint32_t)__cvta_generic_to_shared(&mbar_store[1]);
    empty[0] = (uint32_t)__cvta_generic_to_shared(&mbar_store[2]);
    empty[1] = (uint32_t)__cvta_generic_to_shared(&mbar_store[3]);

    if (t == 0) {
        mbar_init(full[0], 1);
        mbar_init(full[1], 1);
        mbar_init(empty[0], NTHREADS);
        mbar_init(empty[1], NTHREADS);
        asm volatile("fence.proxy.async.shared::cta;" ::: "memory");
    }

    // Preload x and quantile offsets for the (64 batch x len) tile.
    {
        const int bl    = t >> 3;        // 0..63
        const int lane8 = t & 7;
        const float* xp = x       + (size_t)(b0 + bl) * SIZE_IN + lo;
        const int*   qp = indices + (size_t)(b0 + bl) * SIZE_IN + lo;
        #pragma unroll
        for (int k = 0; k < 4; k++) {
            const int ii = lane8 + k * 8;
            if (ii < len)
                sxq[bl][ii] = make_float2(xp[ii], __int_as_float(qp[ii] * SIZE_OUT));
        }
    }

    __syncthreads();   // mbar init + sxq visible before first bulk issue / reads

    const uint32_t sW0 = (uint32_t)__cvta_generic_to_shared(sW);
    if (t == 0) stage_phase(sW0, table, lo, (len >= 2) ? 2 : 1, full[0]);

    float4 acc[8];
    #pragma unroll
    for (int k = 0; k < 8; k++) acc[k] = make_float4(0.f, 0.f, 0.f, 0.f);

    for (int p = 0; p < nph; p++) {
        const int buf = p & 1;

        // t0: stage phase p+1 into the other buffer once its previous readers drained.
        if (t == 0 && p + 1 < nph) {
            if (p >= 1) mbar_wait(empty[buf ^ 1], (uint32_t)(((p - 1) >> 1) & 1));
            const int i0 = lo + 2 * (p + 1);
            const int nf = (len - 2 * (p + 1) >= 2) ? 2 : 1;
            stage_phase(sW0 + (uint32_t)(buf ^ 1) * 32768u, table, i0, nf, full[buf ^ 1]);
        }

        mbar_wait(full[buf], (uint32_t)((p >> 1) & 1));

        const float* wb  = sW + (buf << 13);     // 8192 floats per buffer
        const int    ii0 = 2 * p;
        const bool   two = (ii0 + 1 < len);

        #pragma unroll
        for (int bl = 0; bl < 8; bl++) {
            const int b = bg * 8 + bl;                      // uniform per warp
            const float2 v = sxq[b][ii0];
            const float4 w = *reinterpret_cast<const float4*>(
                wb + __float_as_int(v.y) + og * 4);
            acc[bl].x += v.x * w.x;
            acc[bl].y += v.x * w.y;
            acc[bl].z += v.x * w.z;
            acc[bl].w += v.x * w.w;
        }
        if (two) {
            #pragma unroll
            for (int bl = 0; bl < 8; bl++) {
                const int b = bg * 8 + bl;
                const float2 v = sxq[b][ii0 + 1];
                const float4 w = *reinterpret_cast<const float4*>(
                    wb + 4096 + __float_as_int(v.y) + og * 4);
                acc[bl].x += v.x * w.x;
                acc[bl].y += v.x * w.y;
                acc[bl].z += v.x * w.z;
                acc[bl].w += v.x * w.w;
            }
        }

        mbar_arrive(empty[buf]);   // this thread is done reading sW[buf]
    }

    // Combine split-k partials.
    #pragma unroll
    for (int bl = 0; bl < 8; bl++) {
        const int b = b0 + bg * 8 + bl;
        float* op = out + (size_t)b * SIZE_OUT + og * 4;
        atomicAdd(op + 0, acc[bl].x);
        atomicAdd(op + 1, acc[bl].y);
        atomicAdd(op + 2, acc[bl].z);
        atomicAdd(op + 3, acc[bl].w);
    }
}

extern "C" void kernel_launch(void* const* d_in, const int* in_sizes, int n_in,
                              void* d_out, int out_size) {
    const float* x       = (const float*)d_in[0];
    const int*   indices = (const int*)d_in[1];
    const float* table   = (const float*)d_in[2];
    const float* bias    = (const float*)d_in[3];
    float*       out     = (float*)d_out;

    static int attr_set = 0;
    if (!attr_set) {
        cudaFuncSetAttribute(il_main, cudaFuncAttributeMaxDynamicSharedMemorySize, DYN_SMEM);
        attr_set = 1;
    }

    il_init_out<<<(BATCH * SIZE_OUT + 255) / 256, 256>>>(bias, out);

    dim3 grid(BATCH / BT, ISPLIT);   // 8 x 37 = 296 CTAs = 148 SMs * 2
    il_main<<<grid, NTHREADS, DYN_SMEM>>>(x, indices, table, out);
}

// round 9
// speedup vs baseline: 1.7539x; 1.7539x over previous
#include <cuda_runtime.h>
#include <cuda_fp16.h>
#include <cstdint>

#define BATCH     512
#define SIZE_IN   1024
#define SIZE_OUT  256
#define NQ        16

#define BT        64                 // batch tile per CTA
#define ISPLIT    37                 // 8 * 37 = 296 = 148 SMs * 2 CTAs exactly
#define ICHUNKMAX 28                 // ceil(1024/37)
#define NTHREADS  512

// fp16 copy of the weight table (8 MB static scratch; no allocation allowed)
__device__ __half g_tableh[NQ * SIZE_IN * SIZE_OUT];

// out[b,o] = bias[o]  (atomic accumulation target)
__global__ void il_init_out(const float* __restrict__ bias, float* __restrict__ out) {
    int i = blockIdx.x * blockDim.x + threadIdx.x;
    if (i < BATCH * SIZE_OUT) out[i] = bias[i & (SIZE_OUT - 1)];
}

// table fp32 -> fp16, 8 elements per thread (32B read / 16B write, coalesced)
__global__ void il_prep_half(const float* __restrict__ table) {
    const size_t i = ((size_t)blockIdx.x * blockDim.x + threadIdx.x) * 8;
    const float4 a = *reinterpret_cast<const float4*>(table + i);
    const float4 b = *reinterpret_cast<const float4*>(table + i + 4);
    __half2 h[4];
    h[0] = __floats2half2_rn(a.x, a.y);
    h[1] = __floats2half2_rn(a.z, a.w);
    h[2] = __floats2half2_rn(b.x, b.y);
    h[3] = __floats2half2_rn(b.z, b.w);
    *reinterpret_cast<uint4*>(g_tableh + i) = *reinterpret_cast<uint4*>(h);
}

__device__ __forceinline__ void cp_async16(uint32_t saddr, const void* gptr) {
    asm volatile("cp.async.cg.shared.global [%0], [%1], 16;\n" :: "r"(saddr), "l"(gptr));
}
__device__ __forceinline__ void cp_commit() {
    asm volatile("cp.async.commit_group;\n" ::: "memory");
}
__device__ __forceinline__ void cp_wait0() {
    asm volatile("cp.async.wait_group 0;\n" ::: "memory");
}

// One CTA: 64 batches x (27..28) features x 256 outputs.
// Double-buffered 8 KB fp16 weight stage (16 q-rows of current feature),
// cp.async prefetch of feature ii+1 while computing feature ii.
__global__ __launch_bounds__(NTHREADS, 2)
void il_main(const float* __restrict__ x,
             const int* __restrict__ indices,   // JAX canonicalizes int64 -> int32
             float* __restrict__ out) {
    const int b0  = blockIdx.x * BT;
    const int lo  = (int)(((long long)blockIdx.y * SIZE_IN) / ISPLIT);
    const int hi  = (int)(((long long)(blockIdx.y + 1) * SIZE_IN) / ISPLIT);
    const int len = hi - lo;             // 27 or 28
    const int t   = threadIdx.x;
    const int og  = t & 63;              // output columns og*4 .. og*4+3
    const int bg  = t >> 6;              // batches bg*8 .. bg*8+7

    __shared__ __align__(16) __half sW[2][NQ * SIZE_OUT];   // 2 x 8 KB
    __shared__ float2 sxq[BT][ICHUNKMAX];                    // {x, float-bits of q*256}

    const uint32_t sW_u32 = (uint32_t)__cvta_generic_to_shared(&sW[0][0]);

    // This thread's single 16B staging piece per feature: row q, 16B chunk c.
    const int sq = t >> 5;               // 0..15
    const int sc = t & 31;               // 0..31 (32 x 16B = 512B row)

    // Preload x and quantile offsets for the (64 batch x len) tile.
    {
        const int bl    = t >> 3;        // 0..63
        const int lane8 = t & 7;
        const float* xp = x       + (size_t)(b0 + bl) * SIZE_IN + lo;
        const int*   qp = indices + (size_t)(b0 + bl) * SIZE_IN + lo;
        #pragma unroll
        for (int k = 0; k < 4; k++) {
            const int ii = lane8 + k * 8;
            if (ii < len)
                sxq[bl][ii] = make_float2(xp[ii], __int_as_float(qp[ii] * SIZE_OUT));
        }
    }

    float4 acc[8];
    #pragma unroll
    for (int k = 0; k < 8; k++) acc[k] = make_float4(0.f, 0.f, 0.f, 0.f);

    // Prefetch feature lo into buffer 0 (one 16B cp.async per thread).
    cp_async16(sW_u32 + (uint32_t)(sq * 512 + sc * 16),
               g_tableh + ((size_t)sq * SIZE_IN + lo) * SIZE_OUT + sc * 8);
    cp_commit();

    for (int ii = 0; ii < len; ii++) {
        const int buf = ii & 1;

        cp_wait0();
        __syncthreads();   // buf visible to all; all done reading buf^1

        if (ii + 1 < len) {
            cp_async16(sW_u32 + (uint32_t)((buf ^ 1) * 8192 + sq * 512 + sc * 16),
                       g_tableh + ((size_t)sq * SIZE_IN + lo + ii + 1) * SIZE_OUT + sc * 8);
            cp_commit();
        }

        const __half* wb = sW[buf];
        #pragma unroll
        for (int bl = 0; bl < 8; bl++) {
            const int b = bg * 8 + bl;                    // uniform per warp -> LDS broadcast
            const float2 v = sxq[b][ii];                  // {x, q*256 offset in halves}
            const int off = __float_as_int(v.y);
            const uint2 u = *reinterpret_cast<const uint2*>(wb + off + og * 4);
            const float2 f0 = __half22float2(*reinterpret_cast<const __half2*>(&u.x));
            const float2 f1 = __half22float2(*reinterpret_cast<const __half2*>(&u.y));
            acc[bl].x += v.x * f0.x;
            acc[bl].y += v.x * f0.y;
            acc[bl].z += v.x * f1.x;
            acc[bl].w += v.x * f1.y;
        }
    }

    // Combine split-k partials.
    #pragma unroll
    for (int bl = 0; bl < 8; bl++) {
        const int b = b0 + bg * 8 + bl;
        float* op = out + (size_t)b * SIZE_OUT + og * 4;
        atomicAdd(op + 0, acc[bl].x);
        atomicAdd(op + 1, acc[bl].y);
        atomicAdd(op + 2, acc[bl].z);
        atomicAdd(op + 3, acc[bl].w);
    }
}

extern "C" void kernel_launch(void* const* d_in, const int* in_sizes, int n_in,
                              void* d_out, int out_size) {
    const float* x       = (const float*)d_in[0];
    const int*   indices = (const int*)d_in[1];
    const float* table   = (const float*)d_in[2];
    const float* bias    = (const float*)d_in[3];
    float*       out     = (float*)d_out;

    // table -> fp16 (4,194,304 elems / 8 per thread / 256 per block = 2048 blocks)
    il_prep_half<<<2048, 256>>>(table);

    il_init_out<<<(BATCH * SIZE_OUT + 255) / 256, 256>>>(bias, out);

    dim3 grid(BATCH / BT, ISPLIT);   // 8 x 37 = 296 CTAs = 148 SMs * 2
    il_main<<<grid, NTHREADS>>>(x, indices, out);
}